// round 6
// baseline (speedup 1.0000x reference)
#include <cuda_runtime.h>
#include <math.h>
#include <stdint.h>

// ---------------------------------------------------------------------------
// Problem constants
// ---------------------------------------------------------------------------
#define NMAX 50000
#define EMAX 800000
#define DDIM 128
#define HEADS 8
#define FIN 256
#define NCLS 40

// Packed-weight arena layout (floats)
#define WP_WI    0
#define WP_L0    32768
#define WP_LSTR  131072
#define WP_WQ    0
#define WP_WK    16384
#define WP_WV    32768
#define WP_WO    49152
#define WP_WF1   65536
#define WP_WF2   98304
#define WP_WOUT  (WP_L0 + 5 * WP_LSTR)
#define WP_TOTAL (WP_WOUT + 16384)

// ---------------------------------------------------------------------------
// Device scratch
// ---------------------------------------------------------------------------
__device__ float g_h  [NMAX * DDIM];
__device__ float g_q  [NMAX * DDIM];
__device__ float g_k  [NMAX * DDIM];
__device__ float g_v  [NMAX * DDIM];
__device__ float g_xh [NMAX * FIN];
__device__ float g_xl [NMAX * FIN];
__device__ float g_lnh[NMAX * DDIM];
__device__ float g_lnl[NMAX * DDIM];
__device__ float g_agh[NMAX * DDIM];
__device__ float g_agl[NMAX * DDIM];
__device__ float g_ffh[NMAX * 2 * DDIM];
__device__ float g_ffl[NMAX * 2 * DDIM];
__device__ float g_wph[WP_TOTAL];
__device__ float g_wpl[WP_TOTAL];
__device__ int   g_deg [NMAX];
__device__ int   g_cur [NMAX];
__device__ int   g_off [NMAX + 1];
__device__ int   g_srcs[EMAX];

// ---------------------------------------------------------------------------
// TF32 / async-copy helpers
// ---------------------------------------------------------------------------
__device__ __forceinline__ float f2tf32(float x)
{
    uint32_t r;
    asm("cvt.rna.tf32.f32 %0, %1;" : "=r"(r) : "f"(x));
    return __uint_as_float(r);
}

__device__ __forceinline__ void mma_tf32(float* d, const uint32_t* a, const uint32_t* b)
{
    asm volatile(
        "mma.sync.aligned.m16n8k8.row.col.f32.tf32.tf32.f32 "
        "{%0,%1,%2,%3}, {%4,%5,%6,%7}, {%8,%9}, {%0,%1,%2,%3};\n"
        : "+f"(d[0]), "+f"(d[1]), "+f"(d[2]), "+f"(d[3])
        : "r"(a[0]), "r"(a[1]), "r"(a[2]), "r"(a[3]), "r"(b[0]), "r"(b[1]));
}

__device__ __forceinline__ void cp_async16(uint32_t saddr, const void* gptr, bool pred)
{
    int bytes = pred ? 16 : 0;
    asm volatile("cp.async.cg.shared.global [%0], [%1], 16, %2;\n"
                 :: "r"(saddr), "l"(gptr), "r"(bytes));
}
#define CP_COMMIT() asm volatile("cp.async.commit_group;\n" ::: "memory")
#define CP_WAIT0()  asm volatile("cp.async.wait_group 0;\n" ::: "memory")

// ---------------------------------------------------------------------------
// Prep: elementwise hi/lo split (float4 granularity)
// ---------------------------------------------------------------------------
__global__ void split_kernel(const float* __restrict__ src, float* __restrict__ hi,
                             float* __restrict__ lo, int n4)
{
    int t = blockIdx.x * blockDim.x + threadIdx.x;
    if (t >= n4) return;
    float4 v = ((const float4*)src)[t];
    float4 h, l;
    h.x = f2tf32(v.x); l.x = v.x - h.x;
    h.y = f2tf32(v.y); l.y = v.y - h.y;
    h.z = f2tf32(v.z); l.z = v.z - h.z;
    h.w = f2tf32(v.w); l.w = v.w - h.w;
    ((float4*)hi)[t] = h;
    ((float4*)lo)[t] = l;
}

// ---------------------------------------------------------------------------
// Prep: pack weights into mma-fragment-pair layout, split hi/lo.
// Element (k,n): block (nblk = n/128, kb = k/8), offset within 1024-block:
//   (n%128)*8 + (k%4)*2 + ((k>>2)&1)
// ---------------------------------------------------------------------------
__global__ void pack_w_kernel(const float* __restrict__ src, float* __restrict__ hi,
                              float* __restrict__ lo, int K, int Nact, int Npad,
                              int nMat, int srcStride, int dstStride, int dstBase)
{
    long t = (long)blockIdx.x * blockDim.x + threadIdx.x;
    long per = (long)K * Npad;
    if (t >= per * nMat) return;
    int mat = (int)(t / per);
    long r  = t % per;
    int k = (int)(r / Npad);
    int n = (int)(r % Npad);
    float v = (n < Nact) ? src[(size_t)mat * srcStride + (size_t)k * Nact + n] : 0.f;
    float hv = f2tf32(v), lv = v - hv;
    int nblk = n >> 7, nl = n & 127, kb = k >> 3;
    size_t off = (size_t)dstBase + (size_t)mat * dstStride
               + ((size_t)nblk * (K >> 3) + kb) * 1024
               + (nl * 4 + (k & 3)) * 2 + ((k >> 2) & 1);
    hi[off] = hv;
    lo[off] = lv;
}

// ---------------------------------------------------------------------------
// Tensor-core GEMM (3xTF32, pre-split operands), cp.async double-buffer, BK=16
// C[M,N] = op(Ahi+Alo @ Bp + bias [+Res]); K % 16 == 0.
// Block 128x128, 8 warps (4M x 2N), warp tile 32x64.
// Smem stage: Ahi[128x20] Alo[128x20] Bhi[2048] Blo[2048] = 9216 floats.
// ---------------------------------------------------------------------------
#define BK 16
#define A_ST 20
#define SA_LO 2560
#define SB_HI 5120
#define SB_LO 7168
#define STAGE_SZ 9216
#define GEMM_SMEM_BYTES (2 * STAGE_SZ * (int)sizeof(float))

template <bool RELU, bool RES, bool SPLIT>
__device__ __forceinline__ void gemm_tc_body(
    float* __restrict__ sm,
    const float* __restrict__ Ahi, const float* __restrict__ Alo,
    const float* __restrict__ BpHi, const float* __restrict__ BpLo,
    const float* __restrict__ bias, const float* __restrict__ Rsd,
    float* __restrict__ C, float* __restrict__ Chi, float* __restrict__ Clo,
    int M, int N, int K)
{
    const int tid  = threadIdx.x;
    const int lane = tid & 31;
    const int wid  = tid >> 5;
    const int g    = lane >> 2;
    const int c    = lane & 3;
    const int wm   = (wid >> 1) * 32;
    const int wn   = (wid & 1) * 64;

    const int row0 = blockIdx.y * 128;
    const int col0 = blockIdx.x * 128;

    // This block's packed-B region
    BpHi += (size_t)blockIdx.x * (K >> 3) * 1024;
    BpLo += (size_t)blockIdx.x * (K >> 3) * 1024;

    const uint32_t smBase = (uint32_t)__cvta_generic_to_shared(sm);

    auto loadTile = [&](int st, int kt) {
        int k0 = kt * BK;
        #pragma unroll
        for (int j = 0; j < 2; j++) {
            int id = tid + j * 256;
            // A: 128 rows x 16 floats per half
            int r  = id >> 2;
            int c4 = (id & 3) << 2;
            int ar = row0 + r;
            bool ok = ar < M;
            size_t gofs = (size_t)(ok ? ar : 0) * K + k0 + c4;
            uint32_t da = smBase + (uint32_t)((st * STAGE_SZ + r * A_ST + c4) * 4);
            cp_async16(da, Ahi + gofs, ok);
            cp_async16(da + SA_LO * 4, Alo + gofs, ok);
            // B: 2048 contiguous floats per half (two 1024 k8-blocks)
            size_t bofs = (size_t)kt * 2048 + (size_t)id * 4;
            uint32_t db = smBase + (uint32_t)((st * STAGE_SZ + SB_HI + id * 4) * 4);
            cp_async16(db, BpHi + bofs, true);
            cp_async16(db + 2048 * 4, BpLo + bofs, true);
        }
    };

    float acc[2][8][4] = {};

    const int KT = K / BK;
    loadTile(0, 0);
    CP_COMMIT();

    for (int kt = 0; kt < KT; kt++) {
        CP_WAIT0();
        __syncthreads();
        if (kt + 1 < KT) {
            loadTile((kt + 1) & 1, kt + 1);
            CP_COMMIT();
        }

        const float* S   = sm + (kt & 1) * STAGE_SZ;
        const float* AsH = S;
        const float* AsL = S + SA_LO;
        const float* BsH = S + SB_HI;
        const float* BsL = S + SB_LO;

        #pragma unroll
        for (int kk = 0; kk < 2; kk++) {
            uint32_t aH[2][4], aL[2][4];
            #pragma unroll
            for (int t = 0; t < 2; t++) {
                int o = (wm + 16 * t + g) * A_ST + kk * 8 + c;
                aH[t][0] = __float_as_uint(AsH[o]);
                aH[t][1] = __float_as_uint(AsH[o + 8 * A_ST]);
                aH[t][2] = __float_as_uint(AsH[o + 4]);
                aH[t][3] = __float_as_uint(AsH[o + 8 * A_ST + 4]);
                aL[t][0] = __float_as_uint(AsL[o]);
                aL[t][1] = __float_as_uint(AsL[o + 8 * A_ST]);
                aL[t][2] = __float_as_uint(AsL[o + 4]);
                aL[t][3] = __float_as_uint(AsL[o + 8 * A_ST + 4]);
            }
            #pragma unroll
            for (int jh = 0; jh < 2; jh++) {
                uint2 bH[4], bL[4];
                #pragma unroll
                for (int j = 0; j < 4; j++) {
                    int n = wn + 8 * (jh * 4 + j) + g;
                    int o = kk * 1024 + (n * 4 + c) * 2;
                    bH[j] = *(const uint2*)&BsH[o];
                    bL[j] = *(const uint2*)&BsL[o];
                }
                #pragma unroll
                for (int t = 0; t < 2; t++)
                    #pragma unroll
                    for (int j = 0; j < 4; j++) {
                        float* d = acc[t][jh * 4 + j];
                        mma_tf32(d, aH[t], (const uint32_t*)&bH[j]);
                        mma_tf32(d, aL[t], (const uint32_t*)&bH[j]);
                        mma_tf32(d, aH[t], (const uint32_t*)&bL[j]);
                    }
            }
        }
        __syncthreads();
    }

    // ---- Epilogue: thread owns rows {wm+16t+g, +8}, cols {wn+8j+2c, +1}
    #pragma unroll
    for (int t = 0; t < 2; t++) {
        #pragma unroll
        for (int rr = 0; rr < 2; rr++) {
            int r = row0 + wm + 16 * t + g + rr * 8;
            if (r >= M) continue;
            #pragma unroll
            for (int j = 0; j < 8; j++) {
                int cc = col0 + wn + 8 * j + 2 * c;
                if (cc >= N) continue;
                float v0 = acc[t][j][rr * 2 + 0] + bias[cc];
                float v1 = acc[t][j][rr * 2 + 1] + bias[cc + 1];
                if (RELU) { v0 = fmaxf(v0, 0.f); v1 = fmaxf(v1, 0.f); }
                if (RES) {
                    float2 rv = *(const float2*)(Rsd + (size_t)r * N + cc);
                    v0 += rv.x; v1 += rv.y;
                }
                if (SPLIT) {
                    float h0 = f2tf32(v0), h1 = f2tf32(v1);
                    float2 hv; hv.x = h0; hv.y = h1;
                    float2 lv; lv.x = v0 - h0; lv.y = v1 - h1;
                    *(float2*)(Chi + (size_t)r * N + cc) = hv;
                    *(float2*)(Clo + (size_t)r * N + cc) = lv;
                } else {
                    float2 out; out.x = v0; out.y = v1;
                    *(float2*)(C + (size_t)r * N + cc) = out;
                }
            }
        }
    }
}

template <bool RELU, bool RES, bool SPLIT>
__global__ __launch_bounds__(256, 2) void gemm_tc_kernel(
    const float* __restrict__ Ahi, const float* __restrict__ Alo,
    const float* __restrict__ BpHi, const float* __restrict__ BpLo,
    const float* __restrict__ bias, const float* __restrict__ Rsd,
    float* __restrict__ C, float* __restrict__ Chi, float* __restrict__ Clo,
    int M, int N, int K)
{
    extern __shared__ float sm[];
    gemm_tc_body<RELU, RES, SPLIT>(sm, Ahi, Alo, BpHi, BpLo, bias, Rsd, C, Chi, Clo, M, N, K);
}

__global__ __launch_bounds__(256, 2) void gemm_qkv_kernel(
    const float* __restrict__ Ahi, const float* __restrict__ Alo,
    const float* __restrict__ wph, const float* __restrict__ wpl,
    const float* __restrict__ bq, const float* __restrict__ bk, const float* __restrict__ bv,
    float* __restrict__ q, float* __restrict__ k, float* __restrict__ v, int M)
{
    extern __shared__ float sm[];
    const float* BH; const float* BL; const float* bias; float* C;
    if (blockIdx.z == 0)      { BH = wph + WP_WQ; BL = wpl + WP_WQ; bias = bq; C = q; }
    else if (blockIdx.z == 1) { BH = wph + WP_WK; BL = wpl + WP_WK; bias = bk; C = k; }
    else                      { BH = wph + WP_WV; BL = wpl + WP_WV; bias = bv; C = v; }
    gemm_tc_body<false, false, false>(sm, Ahi, Alo, BH, BL, bias, nullptr, C, nullptr, nullptr,
                                      M, DDIM, DDIM);
}

// ---------------------------------------------------------------------------
// LayerNorm over D=128 -> split hi/lo output
// ---------------------------------------------------------------------------
__global__ void ln_kernel(const float* __restrict__ X, const float* __restrict__ g,
                          const float* __restrict__ b, float* __restrict__ Yh,
                          float* __restrict__ Yl, int n)
{
    int row = blockIdx.x * 8 + threadIdx.y;
    if (row >= n) return;
    int lane = threadIdx.x;
    float4 x = *(const float4*)(X + (size_t)row * DDIM + lane * 4);
    float s  = x.x + x.y + x.z + x.w;
    float ss = x.x * x.x + x.y * x.y + x.z * x.z + x.w * x.w;
    #pragma unroll
    for (int o = 16; o > 0; o >>= 1) {
        s  += __shfl_xor_sync(0xffffffffu, s, o);
        ss += __shfl_xor_sync(0xffffffffu, ss, o);
    }
    float mu  = s * (1.f / DDIM);
    float var = ss * (1.f / DDIM) - mu * mu;
    float rstd = rsqrtf(var + 1e-5f);
    float4 gv = *(const float4*)(g + lane * 4);
    float4 bv = *(const float4*)(b + lane * 4);
    float4 y;
    y.x = (x.x - mu) * rstd * gv.x + bv.x;
    y.y = (x.y - mu) * rstd * gv.y + bv.y;
    y.z = (x.z - mu) * rstd * gv.z + bv.z;
    y.w = (x.w - mu) * rstd * gv.w + bv.w;
    float4 h, l;
    h.x = f2tf32(y.x); l.x = y.x - h.x;
    h.y = f2tf32(y.y); l.y = y.y - h.y;
    h.z = f2tf32(y.z); l.z = y.z - h.z;
    h.w = f2tf32(y.w); l.w = y.w - h.w;
    *(float4*)(Yh + (size_t)row * DDIM + lane * 4) = h;
    *(float4*)(Yl + (size_t)row * DDIM + lane * 4) = l;
}

// ---------------------------------------------------------------------------
// CSR build (edges grouped by destination) — once per launch
// ---------------------------------------------------------------------------
__global__ void hist_kernel(const int* __restrict__ dst, int* __restrict__ deg, int E)
{
    int t = blockIdx.x * blockDim.x + threadIdx.x;
    if (t < E) atomicAdd(&deg[dst[t]], 1);
}

__global__ void scan_kernel(const int* __restrict__ deg, int* __restrict__ off, int n)
{
    const int T = 1024;
    __shared__ int sm[T];
    int t = threadIdx.x;
    int chunk = (n + T - 1) / T;
    int b = t * chunk;
    int e = min(n, b + chunk);
    int s = 0;
    for (int i = b; i < e; i++) s += deg[i];
    sm[t] = s;
    __syncthreads();
    for (int o = 1; o < T; o <<= 1) {
        int add = (t >= o) ? sm[t - o] : 0;
        __syncthreads();
        sm[t] += add;
        __syncthreads();
    }
    int excl = (t > 0) ? sm[t - 1] : 0;
    for (int i = b; i < e; i++) { off[i] = excl; excl += deg[i]; }
    if (t == T - 1) off[n] = excl;
}

__global__ void scatter_kernel(const int* __restrict__ src, const int* __restrict__ dst,
                               int* __restrict__ cur, int* __restrict__ srcs, int E)
{
    int t = blockIdx.x * blockDim.x + threadIdx.x;
    if (t < E) {
        int p = atomicAdd(&cur[dst[t]], 1);
        srcs[p] = src[t];
    }
}

// ---------------------------------------------------------------------------
// Fused edge-softmax attention -> split hi/lo output
// ---------------------------------------------------------------------------
__global__ void attn_kernel(const float* __restrict__ q, const float* __restrict__ k,
                            const float* __restrict__ v, const int* __restrict__ off,
                            const int* __restrict__ srcs, float* __restrict__ aggH,
                            float* __restrict__ aggL, int n)
{
    int node = blockIdx.x * 8 + threadIdx.y;
    if (node >= n) return;
    int lane = threadIdx.x;

    float4 kf = *(const float4*)(k + (size_t)node * DDIM + lane * 4);
    int beg = off[node], end = off[node + 1];

    float m = -INFINITY, ssum = 0.f;
    float4 acc = make_float4(0.f, 0.f, 0.f, 0.f);

    for (int j = beg; j < end; j++) {
        int s = srcs[j];
        float4 qa = *(const float4*)(q + (size_t)s * DDIM + lane * 4);
        float p = qa.x * kf.x + qa.y * kf.y + qa.z * kf.z + qa.w * kf.w;
        p += __shfl_xor_sync(0xffffffffu, p, 1);
        p += __shfl_xor_sync(0xffffffffu, p, 2);
        p *= 0.25f;  // 1/sqrt(HD=16)

        float mn = fmaxf(m, p);
        float scale = __expf(m - mn);
        float w = __expf(p - mn);
        ssum = ssum * scale + w;

        float4 vv = *(const float4*)(v + (size_t)s * DDIM + lane * 4);
        acc.x = acc.x * scale + w * vv.x;
        acc.y = acc.y * scale + w * vv.y;
        acc.z = acc.z * scale + w * vv.z;
        acc.w = acc.w * scale + w * vv.w;
        m = mn;
    }

    float inv = (end > beg) ? 1.f / ssum : 0.f;
    float4 o, h, l;
    o.x = acc.x * inv; o.y = acc.y * inv; o.z = acc.z * inv; o.w = acc.w * inv;
    h.x = f2tf32(o.x); l.x = o.x - h.x;
    h.y = f2tf32(o.y); l.y = o.y - h.y;
    h.z = f2tf32(o.z); l.z = o.z - h.z;
    h.w = f2tf32(o.w); l.w = o.w - h.w;
    *(float4*)(aggH + (size_t)node * DDIM + lane * 4) = h;
    *(float4*)(aggL + (size_t)node * DDIM + lane * 4) = l;
}

// ---------------------------------------------------------------------------
// Host orchestration
// ---------------------------------------------------------------------------
extern "C" void kernel_launch(void* const* d_in, const int* in_sizes, int n_in,
                              void* d_out, int out_size)
{
    const float* x    = (const float*)d_in[0];
    const int*   esrc = (const int*)  d_in[1];
    const int*   edst = (const int*)  d_in[2];
    const float* Wi   = (const float*)d_in[3];
    const float* bi   = (const float*)d_in[4];
    const float* Wq   = (const float*)d_in[5];
    const float* bq   = (const float*)d_in[6];
    const float* Wk   = (const float*)d_in[7];
    const float* bk   = (const float*)d_in[8];
    const float* Wv   = (const float*)d_in[9];
    const float* bv   = (const float*)d_in[10];
    const float* Wo   = (const float*)d_in[11];
    const float* bo   = (const float*)d_in[12];
    const float* g1   = (const float*)d_in[13];
    const float* b1   = (const float*)d_in[14];
    const float* Wf1  = (const float*)d_in[15];
    const float* bf1  = (const float*)d_in[16];
    const float* Wf2  = (const float*)d_in[17];
    const float* bf2  = (const float*)d_in[18];
    const float* gout = (const float*)d_in[19];
    const float* boutg= (const float*)d_in[20];
    const float* Wout = (const float*)d_in[21];
    const float* bout = (const float*)d_in[22];

    const int Nn = in_sizes[0] / FIN;   // 50000
    const int Ee = in_sizes[1];         // 800000

    float *h, *q, *k, *v, *xh, *xl, *lnh, *lnl, *agh, *agl, *ffh, *ffl, *wph, *wpl;
    int *deg, *cur, *off, *srcs;
    cudaGetSymbolAddress((void**)&h,    g_h);
    cudaGetSymbolAddress((void**)&q,    g_q);
    cudaGetSymbolAddress((void**)&k,    g_k);
    cudaGetSymbolAddress((void**)&v,    g_v);
    cudaGetSymbolAddress((void**)&xh,   g_xh);
    cudaGetSymbolAddress((void**)&xl,   g_xl);
    cudaGetSymbolAddress((void**)&lnh,  g_lnh);
    cudaGetSymbolAddress((void**)&lnl,  g_lnl);
    cudaGetSymbolAddress((void**)&agh,  g_agh);
    cudaGetSymbolAddress((void**)&agl,  g_agl);
    cudaGetSymbolAddress((void**)&ffh,  g_ffh);
    cudaGetSymbolAddress((void**)&ffl,  g_ffl);
    cudaGetSymbolAddress((void**)&wph,  g_wph);
    cudaGetSymbolAddress((void**)&wpl,  g_wpl);
    cudaGetSymbolAddress((void**)&deg,  g_deg);
    cudaGetSymbolAddress((void**)&cur,  g_cur);
    cudaGetSymbolAddress((void**)&off,  g_off);
    cudaGetSymbolAddress((void**)&srcs, g_srcs);

    cudaFuncSetAttribute(gemm_tc_kernel<false, false, false>, cudaFuncAttributeMaxDynamicSharedMemorySize, GEMM_SMEM_BYTES);
    cudaFuncSetAttribute(gemm_tc_kernel<true,  false, false>, cudaFuncAttributeMaxDynamicSharedMemorySize, GEMM_SMEM_BYTES);
    cudaFuncSetAttribute(gemm_tc_kernel<false, true,  false>, cudaFuncAttributeMaxDynamicSharedMemorySize, GEMM_SMEM_BYTES);
    cudaFuncSetAttribute(gemm_tc_kernel<true,  false, true>,  cudaFuncAttributeMaxDynamicSharedMemorySize, GEMM_SMEM_BYTES);
    cudaFuncSetAttribute(gemm_qkv_kernel,                     cudaFuncAttributeMaxDynamicSharedMemorySize, GEMM_SMEM_BYTES);

    const int mb = (Nn + 127) / 128;
    const dim3 gD(1, mb);
    const dim3 gQKV(1, mb, 3);
    const dim3 gF(2, mb);
    const dim3 gC(1, mb);
    const int lnBlocks = (Nn + 7) / 8;
    const dim3 warpRows(32, 8);
    const int eBlocks = (Ee + 255) / 256;
    const int nodeBlocks = (Nn + 7) / 8;

    // ---- Prep: split x, pack+split weights (once per launch)
    {
        int n4 = Nn * FIN / 4;
        split_kernel<<<(n4 + 255) / 256, 256>>>(x, xh, xl, n4);
        // Wi: K=256, N=128
        pack_w_kernel<<<(256 * 128 + 255) / 256, 256>>>(Wi, wph, wpl, 256, 128, 128, 1, 0, 0, WP_WI);
        // Per-layer weights, batched over L=5
        pack_w_kernel<<<(5 * 128 * 128 + 255) / 256, 256>>>(Wq, wph, wpl, 128, 128, 128, 5, 16384, WP_LSTR, WP_L0 + WP_WQ);
        pack_w_kernel<<<(5 * 128 * 128 + 255) / 256, 256>>>(Wk, wph, wpl, 128, 128, 128, 5, 16384, WP_LSTR, WP_L0 + WP_WK);
        pack_w_kernel<<<(5 * 128 * 128 + 255) / 256, 256>>>(Wv, wph, wpl, 128, 128, 128, 5, 16384, WP_LSTR, WP_L0 + WP_WV);
        pack_w_kernel<<<(5 * 128 * 128 + 255) / 256, 256>>>(Wo, wph, wpl, 128, 128, 128, 5, 16384, WP_LSTR, WP_L0 + WP_WO);
        pack_w_kernel<<<(5 * 128 * 256 + 255) / 256, 256>>>(Wf1, wph, wpl, 128, 256, 256, 5, 32768, WP_LSTR, WP_L0 + WP_WF1);
        pack_w_kernel<<<(5 * 256 * 128 + 255) / 256, 256>>>(Wf2, wph, wpl, 256, 128, 128, 5, 32768, WP_LSTR, WP_L0 + WP_WF2);
        // Wout: K=128, Nact=40 padded to 128
        pack_w_kernel<<<(128 * 128 + 255) / 256, 256>>>(Wout, wph, wpl, 128, 40, 128, 1, 0, 0, WP_WOUT);
    }

    // ---- CSR build
    cudaMemsetAsync(deg, 0, Nn * sizeof(int));
    hist_kernel<<<eBlocks, 256>>>(edst, deg, Ee);
    scan_kernel<<<1, 1024>>>(deg, off, Nn);
    cudaMemcpyAsync(cur, off, Nn * sizeof(int), cudaMemcpyDeviceToDevice);
    scatter_kernel<<<eBlocks, 256>>>(esrc, edst, cur, srcs, Ee);

    // h = relu(x @ Wi + bi)
    gemm_tc_kernel<true, false, false><<<gD, 256, GEMM_SMEM_BYTES>>>(
        xh, xl, wph + WP_WI, wpl + WP_WI, bi, nullptr, h, nullptr, nullptr, Nn, DDIM, FIN);

    for (int i = 0; i < 5; i++) {
        const size_t wl = WP_L0 + (size_t)i * WP_LSTR;

        ln_kernel<<<lnBlocks, warpRows>>>(h, g1 + i * DDIM, b1 + i * DDIM, lnh, lnl, Nn);
        gemm_qkv_kernel<<<gQKV, 256, GEMM_SMEM_BYTES>>>(
            lnh, lnl, wph + wl, wpl + wl,
            bq + i * DDIM, bk + i * DDIM, bv + i * DDIM, q, k, v, Nn);

        attn_kernel<<<nodeBlocks, warpRows>>>(q, k, v, off, srcs, agh, agl, Nn);

        gemm_tc_kernel<false, true, false><<<gD, 256, GEMM_SMEM_BYTES>>>(
            agh, agl, wph + wl + WP_WO, wpl + wl + WP_WO, bo + i * DDIM, h, h,
            nullptr, nullptr, Nn, DDIM, DDIM);

        ln_kernel<<<lnBlocks, warpRows>>>(h, g1 + i * DDIM, b1 + i * DDIM, lnh, lnl, Nn);
        gemm_tc_kernel<true, false, true><<<gF, 256, GEMM_SMEM_BYTES>>>(
            lnh, lnl, wph + wl + WP_WF1, wpl + wl + WP_WF1, bf1 + i * 2 * DDIM, nullptr,
            nullptr, ffh, ffl, Nn, 2 * DDIM, DDIM);
        gemm_tc_kernel<false, true, false><<<gD, 256, GEMM_SMEM_BYTES>>>(
            ffh, ffl, wph + wl + WP_WF2, wpl + wl + WP_WF2, bf2 + i * DDIM, h, h,
            nullptr, nullptr, Nn, DDIM, 2 * DDIM);
    }

    // mid = h
    cudaMemcpyAsync(d_out, h, (size_t)Nn * DDIM * sizeof(float), cudaMemcpyDeviceToDevice);
    // out = LN(h) @ Wout + bout
    ln_kernel<<<lnBlocks, warpRows>>>(h, gout, boutg, lnh, lnl, Nn);
    gemm_tc_kernel<false, false, false><<<gC, 256, GEMM_SMEM_BYTES>>>(
        lnh, lnl, wph + WP_WOUT, wpl + WP_WOUT, bout, nullptr,
        (float*)d_out + (size_t)Nn * DDIM, nullptr, nullptr, Nn, NCLS, DDIM);
}

// round 7
// speedup vs baseline: 1.3641x; 1.3641x over previous
#include <cuda_runtime.h>
#include <cuda_bf16.h>
#include <math.h>
#include <stdint.h>

// ---------------------------------------------------------------------------
// Problem constants
// ---------------------------------------------------------------------------
#define NMAX 50000
#define EMAX 800000
#define DDIM 128
#define HEADS 8
#define FIN 256
#define NCLS 40

// Packed-weight arena (uint4 units). Per 128-col block of 16 k: 512 uint4.
#define WP_WI    0            // K=256,N=128 -> 8192
#define WP_L0    8192
#define WPO_Q    0
#define WPO_K    4096
#define WPO_V    8192
#define WPO_O    12288
#define WPO_F1   16384        // K=128,N=256 -> 8192
#define WPO_F2   24576        // K=256,N=128 -> 8192
#define WP_LSTR  32768
#define WP_WOUT  (WP_L0 + 5 * WP_LSTR)   // K=128,N=128pad -> 4096
#define WP_TOTAL (WP_WOUT + 4096)

// ---------------------------------------------------------------------------
// Device scratch
// ---------------------------------------------------------------------------
__device__ float g_h  [NMAX * DDIM];
__device__ float g_q  [NMAX * DDIM];
__device__ float g_k  [NMAX * DDIM];
__device__ float g_v  [NMAX * DDIM];
__device__ uint2 g_x2 [NMAX * FIN / 2];       // x interleaved bf16 hi/lo pairs
__device__ uint2 g_ln2[NMAX * DDIM / 2];
__device__ uint2 g_ag2[NMAX * DDIM / 2];
__device__ uint2 g_ff2[NMAX * DDIM];          // 256 cols -> 128 pairs
__device__ uint4 g_wp [WP_TOTAL];
__device__ int   g_deg [NMAX];
__device__ int   g_cur [NMAX];
__device__ int   g_off [NMAX + 1];
__device__ int   g_srcs[EMAX];

// ---------------------------------------------------------------------------
// Helpers
// ---------------------------------------------------------------------------
__device__ __forceinline__ unsigned pack_bf2(float a, float b)
{
    __nv_bfloat162 t = __floats2bfloat162_rn(a, b);
    return *reinterpret_cast<unsigned*>(&t);
}

// split float4 (4 consecutive k) -> uint4 {hi01, lo01, hi23, lo23}
__device__ __forceinline__ uint4 split4(float4 v)
{
    float h0 = __bfloat162float(__float2bfloat16_rn(v.x));
    float h1 = __bfloat162float(__float2bfloat16_rn(v.y));
    float h2 = __bfloat162float(__float2bfloat16_rn(v.z));
    float h3 = __bfloat162float(__float2bfloat16_rn(v.w));
    uint4 u;
    u.x = pack_bf2(h0, h1);
    u.y = pack_bf2(v.x - h0, v.y - h1);
    u.z = pack_bf2(h2, h3);
    u.w = pack_bf2(v.z - h2, v.w - h3);
    return u;
}

__device__ __forceinline__ void mma_bf16(float* d, const uint32_t* a, const uint32_t* b)
{
    asm volatile(
        "mma.sync.aligned.m16n8k16.row.col.f32.bf16.bf16.f32 "
        "{%0,%1,%2,%3}, {%4,%5,%6,%7}, {%8,%9}, {%0,%1,%2,%3};\n"
        : "+f"(d[0]), "+f"(d[1]), "+f"(d[2]), "+f"(d[3])
        : "r"(a[0]), "r"(a[1]), "r"(a[2]), "r"(a[3]), "r"(b[0]), "r"(b[1]));
}

__device__ __forceinline__ void cp_async16(uint32_t saddr, const void* gptr, bool pred)
{
    int bytes = pred ? 16 : 0;
    asm volatile("cp.async.cg.shared.global [%0], [%1], 16, %2;\n"
                 :: "r"(saddr), "l"(gptr), "r"(bytes));
}
#define CP_COMMIT() asm volatile("cp.async.commit_group;\n" ::: "memory")
#define CP_WAIT0()  asm volatile("cp.async.wait_group 0;\n" ::: "memory")

// ---------------------------------------------------------------------------
// Prep: split x into interleaved bf16 pairs
// ---------------------------------------------------------------------------
__global__ void split_x_kernel(const float* __restrict__ src, uint4* __restrict__ dst, int n4)
{
    int t = blockIdx.x * blockDim.x + threadIdx.x;
    if (t >= n4) return;
    dst[t] = split4(((const float4*)src)[t]);
}

// ---------------------------------------------------------------------------
// Prep: pack weights into mma fragment order, bf16 hi/lo.
// Per (nblk,kb) block of 128 cols x 16 k: entry (nl, c) is a uint4
// {bf2(W[k0+2c][n],W[k0+2c+1][n]), bf2(W[k0+2c+8][n],W[k0+2c+9][n]), lo same}.
// ---------------------------------------------------------------------------
__global__ void pack_w_kernel(const float* __restrict__ src, uint4* __restrict__ dst,
                              int K, int Nact, int Npad, int nMat,
                              int srcStride, int dstStride, int dstBase)
{
    long t = (long)blockIdx.x * blockDim.x + threadIdx.x;
    long per = (long)K * Npad / 4;
    if (t >= per * nMat) return;
    int mat = (int)(t / per);
    long r  = t % per;
    int c   = (int)(r & 3);
    long na = r >> 2;
    int nl  = (int)(na & 127);
    int blk = (int)(na >> 7);
    int kb  = blk % (K >> 4);
    int nbk = blk / (K >> 4);
    int n   = nbk * 128 + nl;
    int k0  = kb * 16 + 2 * c;

    const float* W = src + (size_t)mat * srcStride;
    float va = 0.f, vb = 0.f, vc = 0.f, vd = 0.f;
    if (n < Nact) {
        va = W[(size_t)(k0 + 0) * Nact + n];
        vb = W[(size_t)(k0 + 1) * Nact + n];
        vc = W[(size_t)(k0 + 8) * Nact + n];
        vd = W[(size_t)(k0 + 9) * Nact + n];
    }
    float ha = __bfloat162float(__float2bfloat16_rn(va));
    float hb = __bfloat162float(__float2bfloat16_rn(vb));
    float hc = __bfloat162float(__float2bfloat16_rn(vc));
    float hd = __bfloat162float(__float2bfloat16_rn(vd));
    uint4 u;
    u.x = pack_bf2(ha, hb);
    u.y = pack_bf2(hc, hd);
    u.z = pack_bf2(va - ha, vb - hb);
    u.w = pack_bf2(vc - hc, vd - hd);
    dst[(size_t)dstBase + (size_t)mat * dstStride + (size_t)blk * 512 + nl * 4 + c] = u;
}

// ---------------------------------------------------------------------------
// BF16 3-term tensor-core GEMM, cp.async double-buffered, BK=32.
// A: interleaved bf16 pair rows (uint2 per k-pair). B: packed arena blocks.
// Block 128x128, 8 warps (4M x 2N), warp tile 32x64.
// Smem/stage: A 128 rows x 160B = 20480B, B 2 x 8192B = 16384B.
// ---------------------------------------------------------------------------
#define BK 32
#define A_STB 160
#define SB_OFF 20480
#define STAGE_BYTES 36864
#define GEMM_SMEM_BYTES (2 * STAGE_BYTES)

template <bool RELU, bool RES, bool SPLIT2>
__device__ __forceinline__ void gemm_tc_body(
    const uint2* __restrict__ Ap, const uint4* __restrict__ Bp,
    const float* __restrict__ bias, const float* __restrict__ Rsd,
    float* __restrict__ C, uint2* __restrict__ C2,
    int M, int N, int K)
{
    extern __shared__ __align__(16) char smc[];

    const int tid  = threadIdx.x;
    const int lane = tid & 31;
    const int wid  = tid >> 5;
    const int g    = lane >> 2;
    const int c    = lane & 3;
    const int wm   = (wid >> 1) * 32;
    const int wn   = (wid & 1) * 64;

    const int row0 = blockIdx.y * 128;
    const int col0 = blockIdx.x * 128;

    const char* Bbase = (const char*)(Bp + (size_t)blockIdx.x * (K >> 4) * 512);
    const uint32_t smBase = (uint32_t)__cvta_generic_to_shared(smc);

    auto loadTile = [&](int st, int kt) {
        uint32_t sb = smBase + st * STAGE_BYTES;
        // A: 128 rows x 128B (16 pairs) = 1024 chunks
        #pragma unroll
        for (int i = 0; i < 4; i++) {
            int id = tid + i * 256;
            int r  = id >> 3;
            int ch = id & 7;
            int ar = row0 + r;
            bool ok = ar < M;
            const char* gp = (const char*)Ap
                + ((size_t)(ok ? ar : 0) * (K >> 1) + (size_t)kt * (BK >> 1)) * 8 + ch * 16;
            cp_async16(sb + r * A_STB + ch * 16, gp, ok);
        }
        // B: 16384B = 1024 chunks
        const char* bp = Bbase + (size_t)kt * 16384;
        #pragma unroll
        for (int i = 0; i < 4; i++) {
            int id = tid + i * 256;
            cp_async16(sb + SB_OFF + id * 16, bp + id * 16, true);
        }
    };

    float acc[2][8][4] = {};

    const int KT = K / BK;
    loadTile(0, 0);
    CP_COMMIT();

    for (int kt = 0; kt < KT; kt++) {
        CP_WAIT0();
        __syncthreads();
        if (kt + 1 < KT) {
            loadTile((kt + 1) & 1, kt + 1);
            CP_COMMIT();
        }

        const char* S = smc + (kt & 1) * STAGE_BYTES;

        #pragma unroll
        for (int kk = 0; kk < 2; kk++) {
            uint32_t aH[2][4], aL[2][4];
            #pragma unroll
            for (int t = 0; t < 2; t++) {
                const char* base = S + (wm + 16 * t + g) * A_STB;
                uint2 w0 = *(const uint2*)(base + (kk * 8 + c) * 8);
                uint2 w1 = *(const uint2*)(base + 8 * A_STB + (kk * 8 + c) * 8);
                uint2 w2 = *(const uint2*)(base + (kk * 8 + c + 4) * 8);
                uint2 w3 = *(const uint2*)(base + 8 * A_STB + (kk * 8 + c + 4) * 8);
                aH[t][0] = w0.x; aL[t][0] = w0.y;
                aH[t][1] = w1.x; aL[t][1] = w1.y;
                aH[t][2] = w2.x; aL[t][2] = w2.y;
                aH[t][3] = w3.x; aL[t][3] = w3.y;
            }
            #pragma unroll
            for (int j = 0; j < 8; j++) {
                int n = wn + 8 * j + g;
                uint4 bb = *(const uint4*)(S + SB_OFF + kk * 8192 + (n * 4 + c) * 16);
                uint32_t bH[2] = {bb.x, bb.y};
                uint32_t bL[2] = {bb.z, bb.w};
                #pragma unroll
                for (int t = 0; t < 2; t++) {
                    float* d = acc[t][j];
                    mma_bf16(d, aH[t], bH);
                    mma_bf16(d, aL[t], bH);
                    mma_bf16(d, aH[t], bL);
                }
            }
        }
        __syncthreads();
    }

    // ---- Epilogue: thread owns rows {wm+16t+g, +8}, cols {wn+8j+2c, +1}
    #pragma unroll
    for (int t = 0; t < 2; t++) {
        #pragma unroll
        for (int rr = 0; rr < 2; rr++) {
            int r = row0 + wm + 16 * t + g + rr * 8;
            if (r >= M) continue;
            #pragma unroll
            for (int j = 0; j < 8; j++) {
                int cc = col0 + wn + 8 * j + 2 * c;
                if (cc >= N) continue;
                float v0 = acc[t][j][rr * 2 + 0] + bias[cc];
                float v1 = acc[t][j][rr * 2 + 1] + bias[cc + 1];
                if (RELU) { v0 = fmaxf(v0, 0.f); v1 = fmaxf(v1, 0.f); }
                if (RES) {
                    float2 rv = *(const float2*)(Rsd + (size_t)r * N + cc);
                    v0 += rv.x; v1 += rv.y;
                }
                if (SPLIT2) {
                    float h0 = __bfloat162float(__float2bfloat16_rn(v0));
                    float h1 = __bfloat162float(__float2bfloat16_rn(v1));
                    uint2 u;
                    u.x = pack_bf2(h0, h1);
                    u.y = pack_bf2(v0 - h0, v1 - h1);
                    C2[(size_t)r * (N >> 1) + (cc >> 1)] = u;
                } else {
                    float2 out; out.x = v0; out.y = v1;
                    *(float2*)(C + (size_t)r * N + cc) = out;
                }
            }
        }
    }
}

template <bool RELU, bool RES, bool SPLIT2>
__global__ __launch_bounds__(256, 2) void gemm_tc_kernel(
    const uint2* __restrict__ Ap, const uint4* __restrict__ Bp,
    const float* __restrict__ bias, const float* __restrict__ Rsd,
    float* __restrict__ C, uint2* __restrict__ C2, int M, int N, int K)
{
    gemm_tc_body<RELU, RES, SPLIT2>(Ap, Bp, bias, Rsd, C, C2, M, N, K);
}

__global__ __launch_bounds__(256, 2) void gemm_qkv_kernel(
    const uint2* __restrict__ Ap, const uint4* __restrict__ wp,
    const float* __restrict__ bq, const float* __restrict__ bk, const float* __restrict__ bv,
    float* __restrict__ q, float* __restrict__ k, float* __restrict__ v, int M)
{
    const uint4* Bp; const float* bias; float* C;
    if (blockIdx.z == 0)      { Bp = wp + WPO_Q; bias = bq; C = q; }
    else if (blockIdx.z == 1) { Bp = wp + WPO_K; bias = bk; C = k; }
    else                      { Bp = wp + WPO_V; bias = bv; C = v; }
    gemm_tc_body<false, false, false>(Ap, Bp, bias, nullptr, C, nullptr, M, DDIM, DDIM);
}

// ---------------------------------------------------------------------------
// LayerNorm over D=128 -> interleaved bf16 pair output
// ---------------------------------------------------------------------------
__global__ void ln_kernel(const float* __restrict__ X, const float* __restrict__ g,
                          const float* __restrict__ b, uint4* __restrict__ Y2, int n)
{
    int row = blockIdx.x * 8 + threadIdx.y;
    if (row >= n) return;
    int lane = threadIdx.x;
    float4 x = *(const float4*)(X + (size_t)row * DDIM + lane * 4);
    float s  = x.x + x.y + x.z + x.w;
    float ss = x.x * x.x + x.y * x.y + x.z * x.z + x.w * x.w;
    #pragma unroll
    for (int o = 16; o > 0; o >>= 1) {
        s  += __shfl_xor_sync(0xffffffffu, s, o);
        ss += __shfl_xor_sync(0xffffffffu, ss, o);
    }
    float mu  = s * (1.f / DDIM);
    float var = ss * (1.f / DDIM) - mu * mu;
    float rstd = rsqrtf(var + 1e-5f);
    float4 gv = *(const float4*)(g + lane * 4);
    float4 bv = *(const float4*)(b + lane * 4);
    float4 y;
    y.x = (x.x - mu) * rstd * gv.x + bv.x;
    y.y = (x.y - mu) * rstd * gv.y + bv.y;
    y.z = (x.z - mu) * rstd * gv.z + bv.z;
    y.w = (x.w - mu) * rstd * gv.w + bv.w;
    Y2[(size_t)row * 32 + lane] = split4(y);
}

// ---------------------------------------------------------------------------
// CSR build (edges grouped by destination)
// ---------------------------------------------------------------------------
__global__ void hist_kernel(const int* __restrict__ dst, int* __restrict__ deg, int E)
{
    int t = blockIdx.x * blockDim.x + threadIdx.x;
    if (t < E) atomicAdd(&deg[dst[t]], 1);
}

__global__ void scan_kernel(const int* __restrict__ deg, int* __restrict__ off, int n)
{
    const int T = 1024;
    __shared__ int sm[T];
    int t = threadIdx.x;
    int chunk = (n + T - 1) / T;
    int b = t * chunk;
    int e = min(n, b + chunk);
    int s = 0;
    for (int i = b; i < e; i++) s += deg[i];
    sm[t] = s;
    __syncthreads();
    for (int o = 1; o < T; o <<= 1) {
        int add = (t >= o) ? sm[t - o] : 0;
        __syncthreads();
        sm[t] += add;
        __syncthreads();
    }
    int excl = (t > 0) ? sm[t - 1] : 0;
    for (int i = b; i < e; i++) { off[i] = excl; excl += deg[i]; }
    if (t == T - 1) off[n] = excl;
}

__global__ void scatter_kernel(const int* __restrict__ src, const int* __restrict__ dst,
                               int* __restrict__ cur, int* __restrict__ srcs, int E)
{
    int t = blockIdx.x * blockDim.x + threadIdx.x;
    if (t < E) {
        int p = atomicAdd(&cur[dst[t]], 1);
        srcs[p] = src[t];
    }
}

// ---------------------------------------------------------------------------
// Fused edge-softmax attention -> interleaved bf16 pair output
// ---------------------------------------------------------------------------
__global__ void attn_kernel(const float* __restrict__ q, const float* __restrict__ k,
                            const float* __restrict__ v, const int* __restrict__ off,
                            const int* __restrict__ srcs, uint4* __restrict__ agg2, int n)
{
    int node = blockIdx.x * 8 + threadIdx.y;
    if (node >= n) return;
    int lane = threadIdx.x;

    float4 kf = *(const float4*)(k + (size_t)node * DDIM + lane * 4);
    int beg = off[node], end = off[node + 1];

    float m = -INFINITY, ssum = 0.f;
    float4 acc = make_float4(0.f, 0.f, 0.f, 0.f);

    for (int j = beg; j < end; j++) {
        int s = srcs[j];
        float4 qa = *(const float4*)(q + (size_t)s * DDIM + lane * 4);
        float p = qa.x * kf.x + qa.y * kf.y + qa.z * kf.z + qa.w * kf.w;
        p += __shfl_xor_sync(0xffffffffu, p, 1);
        p += __shfl_xor_sync(0xffffffffu, p, 2);
        p *= 0.25f;  // 1/sqrt(HD=16)

        float mn = fmaxf(m, p);
        float scale = __expf(m - mn);
        float w = __expf(p - mn);
        ssum = ssum * scale + w;

        float4 vv = *(const float4*)(v + (size_t)s * DDIM + lane * 4);
        acc.x = acc.x * scale + w * vv.x;
        acc.y = acc.y * scale + w * vv.y;
        acc.z = acc.z * scale + w * vv.z;
        acc.w = acc.w * scale + w * vv.w;
        m = mn;
    }

    float inv = (end > beg) ? 1.f / ssum : 0.f;
    float4 o;
    o.x = acc.x * inv; o.y = acc.y * inv; o.z = acc.z * inv; o.w = acc.w * inv;
    agg2[(size_t)node * 32 + lane] = split4(o);
}

// ---------------------------------------------------------------------------
// Host orchestration
// ---------------------------------------------------------------------------
extern "C" void kernel_launch(void* const* d_in, const int* in_sizes, int n_in,
                              void* d_out, int out_size)
{
    const float* x    = (const float*)d_in[0];
    const int*   esrc = (const int*)  d_in[1];
    const int*   edst = (const int*)  d_in[2];
    const float* Wi   = (const float*)d_in[3];
    const float* bi   = (const float*)d_in[4];
    const float* Wq   = (const float*)d_in[5];
    const float* bq   = (const float*)d_in[6];
    const float* Wk   = (const float*)d_in[7];
    const float* bk   = (const float*)d_in[8];
    const float* Wv   = (const float*)d_in[9];
    const float* bv   = (const float*)d_in[10];
    const float* Wo   = (const float*)d_in[11];
    const float* bo   = (const float*)d_in[12];
    const float* g1   = (const float*)d_in[13];
    const float* b1   = (const float*)d_in[14];
    const float* Wf1  = (const float*)d_in[15];
    const float* bf1  = (const float*)d_in[16];
    const float* Wf2  = (const float*)d_in[17];
    const float* bf2  = (const float*)d_in[18];
    const float* gout = (const float*)d_in[19];
    const float* boutg= (const float*)d_in[20];
    const float* Wout = (const float*)d_in[21];
    const float* bout = (const float*)d_in[22];

    const int Nn = in_sizes[0] / FIN;   // 50000
    const int Ee = in_sizes[1];         // 800000

    float *h, *q, *k, *v;
    uint2 *x2, *ln2, *ag2, *ff2;
    uint4 *wp;
    int *deg, *cur, *off, *srcs;
    cudaGetSymbolAddress((void**)&h,    g_h);
    cudaGetSymbolAddress((void**)&q,    g_q);
    cudaGetSymbolAddress((void**)&k,    g_k);
    cudaGetSymbolAddress((void**)&v,    g_v);
    cudaGetSymbolAddress((void**)&x2,   g_x2);
    cudaGetSymbolAddress((void**)&ln2,  g_ln2);
    cudaGetSymbolAddress((void**)&ag2,  g_ag2);
    cudaGetSymbolAddress((void**)&ff2,  g_ff2);
    cudaGetSymbolAddress((void**)&wp,   g_wp);
    cudaGetSymbolAddress((void**)&deg,  g_deg);
    cudaGetSymbolAddress((void**)&cur,  g_cur);
    cudaGetSymbolAddress((void**)&off,  g_off);
    cudaGetSymbolAddress((void**)&srcs, g_srcs);

    cudaFuncSetAttribute(gemm_tc_kernel<false, false, false>, cudaFuncAttributeMaxDynamicSharedMemorySize, GEMM_SMEM_BYTES);
    cudaFuncSetAttribute(gemm_tc_kernel<true,  false, false>, cudaFuncAttributeMaxDynamicSharedMemorySize, GEMM_SMEM_BYTES);
    cudaFuncSetAttribute(gemm_tc_kernel<false, true,  false>, cudaFuncAttributeMaxDynamicSharedMemorySize, GEMM_SMEM_BYTES);
    cudaFuncSetAttribute(gemm_tc_kernel<true,  false, true>,  cudaFuncAttributeMaxDynamicSharedMemorySize, GEMM_SMEM_BYTES);
    cudaFuncSetAttribute(gemm_qkv_kernel,                     cudaFuncAttributeMaxDynamicSharedMemorySize, GEMM_SMEM_BYTES);

    const int mb = (Nn + 127) / 128;
    const dim3 gD(1, mb);
    const dim3 gQKV(1, mb, 3);
    const dim3 gF(2, mb);
    const dim3 gC(1, mb);
    const int lnBlocks = (Nn + 7) / 8;
    const dim3 warpRows(32, 8);
    const int eBlocks = (Ee + 255) / 256;
    const int nodeBlocks = (Nn + 7) / 8;

    // ---- Prep (once per launch): split x, pack weights
    {
        int n4 = Nn * FIN / 4;
        split_x_kernel<<<(n4 + 255) / 256, 256>>>(x, (uint4*)x2, n4);
        pack_w_kernel<<<(256 * 128 / 4 + 255) / 256, 256>>>(Wi,  wp, 256, 128, 128, 1, 0, 0, WP_WI);
        pack_w_kernel<<<(5 * 128 * 128 / 4 + 255) / 256, 256>>>(Wq, wp, 128, 128, 128, 5, 16384, WP_LSTR, WP_L0 + WPO_Q);
        pack_w_kernel<<<(5 * 128 * 128 / 4 + 255) / 256, 256>>>(Wk, wp, 128, 128, 128, 5, 16384, WP_LSTR, WP_L0 + WPO_K);
        pack_w_kernel<<<(5 * 128 * 128 / 4 + 255) / 256, 256>>>(Wv, wp, 128, 128, 128, 5, 16384, WP_LSTR, WP_L0 + WPO_V);
        pack_w_kernel<<<(5 * 128 * 128 / 4 + 255) / 256, 256>>>(Wo, wp, 128, 128, 128, 5, 16384, WP_LSTR, WP_L0 + WPO_O);
        pack_w_kernel<<<(5 * 128 * 256 / 4 + 255) / 256, 256>>>(Wf1, wp, 128, 256, 256, 5, 32768, WP_LSTR, WP_L0 + WPO_F1);
        pack_w_kernel<<<(5 * 256 * 128 / 4 + 255) / 256, 256>>>(Wf2, wp, 256, 128, 128, 5, 32768, WP_LSTR, WP_L0 + WPO_F2);
        pack_w_kernel<<<(128 * 128 / 4 + 255) / 256, 256>>>(Wout, wp, 128, 40, 128, 1, 0, 0, WP_WOUT);
    }

    // ---- CSR build
    cudaMemsetAsync(deg, 0, Nn * sizeof(int));
    hist_kernel<<<eBlocks, 256>>>(edst, deg, Ee);
    scan_kernel<<<1, 1024>>>(deg, off, Nn);
    cudaMemcpyAsync(cur, off, Nn * sizeof(int), cudaMemcpyDeviceToDevice);
    scatter_kernel<<<eBlocks, 256>>>(esrc, edst, cur, srcs, Ee);

    // h = relu(x @ Wi + bi)
    gemm_tc_kernel<true, false, false><<<gD, 256, GEMM_SMEM_BYTES>>>(
        x2, wp + WP_WI, bi, nullptr, h, nullptr, Nn, DDIM, FIN);

    for (int i = 0; i < 5; i++) {
        const uint4* wl = wp + WP_L0 + (size_t)i * WP_LSTR;

        ln_kernel<<<lnBlocks, warpRows>>>(h, g1 + i * DDIM, b1 + i * DDIM, (uint4*)ln2, Nn);
        gemm_qkv_kernel<<<gQKV, 256, GEMM_SMEM_BYTES>>>(
            ln2, wl, bq + i * DDIM, bk + i * DDIM, bv + i * DDIM, q, k, v, Nn);

        attn_kernel<<<nodeBlocks, warpRows>>>(q, k, v, off, srcs, (uint4*)ag2, Nn);

        gemm_tc_kernel<false, true, false><<<gD, 256, GEMM_SMEM_BYTES>>>(
            ag2, wl + WPO_O, bo + i * DDIM, h, h, nullptr, Nn, DDIM, DDIM);

        ln_kernel<<<lnBlocks, warpRows>>>(h, g1 + i * DDIM, b1 + i * DDIM, (uint4*)ln2, Nn);
        gemm_tc_kernel<true, false, true><<<gF, 256, GEMM_SMEM_BYTES>>>(
            ln2, wl + WPO_F1, bf1 + i * 2 * DDIM, nullptr, nullptr, ff2, Nn, 2 * DDIM, DDIM);
        gemm_tc_kernel<false, true, false><<<gD, 256, GEMM_SMEM_BYTES>>>(
            ff2, wl + WPO_F2, bf2 + i * DDIM, h, h, nullptr, Nn, DDIM, 2 * DDIM);
    }

    // mid = h
    cudaMemcpyAsync(d_out, h, (size_t)Nn * DDIM * sizeof(float), cudaMemcpyDeviceToDevice);
    // out = LN(h) @ Wout + bout
    ln_kernel<<<lnBlocks, warpRows>>>(h, gout, boutg, (uint4*)ln2, Nn);
    gemm_tc_kernel<false, false, false><<<gC, 256, GEMM_SMEM_BYTES>>>(
        ln2, wp + WP_WOUT, bout, nullptr, (float*)d_out + (size_t)Nn * DDIM, nullptr,
        Nn, NCLS, DDIM);
}